// round 3
// baseline (speedup 1.0000x reference)
#include <cuda_runtime.h>
#include <cuda_fp16.h>
#include <math.h>

#define BB     2
#define NPTS   262144
#define KSLOT  9
#define SDIM   64
#define DDIM   64
#define SCALEF 0.125f

#define TILE    256
#define THREADS 128

// Dynamic smem layout:
//   xs : uint2[256][17]  (16 used = 64 halves/point + 1 pad)  -> 34816 B
//   ws : float[256][12]                                       -> 12288 B
//   As : float[9*64], cs : float[9]
#define XS_U2N   (TILE * 17)            // 4352 uint2
#define WS_OFF   (XS_U2N * 2)           // float index 8704
#define AS_OFF   (WS_OFF + TILE * 12)   // 11776
#define CS_OFF   (AS_OFF + KSLOT * DDIM) // 12352
#define SMEM_BYTES ((CS_OFF + 16) * 4)   // ~49.5 KB

// Precomputed per-batch tiny matrices (written by prep_kernel).
__device__ float g_A[BB][KSLOT][DDIM];   // SCALE * (k @ Wq_w)   [9,64]
__device__ float g_V[BB][KSLOT][DDIM];   // slots_full @ out_w^T [9,64]
__device__ float g_c[BB][KSLOT];         // SCALE * (Wq_b . k_j)
__device__ float g_esc[1];               // exp(density_scale)

// ---------------------------------------------------------------------------
// Prep: one block per batch, 576 threads = (j,d) pairs.
// ---------------------------------------------------------------------------
__global__ void prep_kernel(const float* __restrict__ slots,
                            const float* __restrict__ empty_slot,
                            const float* __restrict__ Wq_w,
                            const float* __restrict__ Wq_b,
                            const float* __restrict__ Wk_w,
                            const float* __restrict__ Wk_b,
                            const float* __restrict__ out_w,
                            const float* __restrict__ density_scale) {
    int b   = blockIdx.x;
    int tid = threadIdx.x;        // 0..575
    int j   = tid >> 6;
    int d   = tid & 63;

    __shared__ float sf[KSLOT][SDIM];
    __shared__ float sk[KSLOT][DDIM];

    sf[j][d] = (j == 0) ? empty_slot[d]
                        : slots[(b * (KSLOT - 1) + (j - 1)) * SDIM + d];
    __syncthreads();

    float kk = Wk_b[d];
    #pragma unroll
    for (int s = 0; s < SDIM; s++)
        kk = fmaf(sf[j][s], Wk_w[d * SDIM + s], kk);
    sk[j][d] = kk;
    __syncthreads();

    float aa = 0.f;
    #pragma unroll
    for (int e = 0; e < DDIM; e++)
        aa = fmaf(sk[j][e], Wq_w[e * DDIM + d], aa);
    g_A[b][j][d] = aa * SCALEF;

    float vv = 0.f;
    #pragma unroll
    for (int s = 0; s < SDIM; s++)
        vv = fmaf(sf[j][s], out_w[d * SDIM + s], vv);
    g_V[b][j][d] = vv;

    if (tid < KSLOT) {
        float cc = 0.f;
        #pragma unroll
        for (int e = 0; e < DDIM; e++)
            cc = fmaf(Wq_b[e], sk[tid][e], cc);
        g_c[b][tid] = cc * SCALEF;
    }
    if (b == 0 && tid == 0) g_esc[0] = expf(density_scale[0]);
}

// ---------------------------------------------------------------------------
// Main: 256 points per 128-thread block, 2 points per thread.
// x staged once as fp16 (halves smem + halves L1 traffic for x).
// ---------------------------------------------------------------------------
__global__ __launch_bounds__(THREADS, 4)
void main_kernel(const float* __restrict__ pf,     // [B,N,64]
                 const float* __restrict__ coor,   // [B,N,3]
                 const float* __restrict__ out_b,  // [64]
                 float* __restrict__ xo_out,       // [B,N,64]
                 float* __restrict__ w_out,        // [B,N,9]
                 float* __restrict__ sig_out) {    // [B,N]

    extern __shared__ float smem[];
    uint2* xs = (uint2*)smem;                     // [TILE][17] (16 used + pad)
    float* ws = smem + WS_OFF;                    // [TILE][12]
    float* As = smem + AS_OFF;                    // [9][64]
    float* cs = smem + CS_OFF;                    // [9]

    const int tid  = threadIdx.x;
    const int base = blockIdx.x * TILE;
    const int b    = base / NPTS;                 // tiles never straddle batches

    // ---- stage A, c ----
    #pragma unroll
    for (int i = tid; i < KSLOT * DDIM; i += THREADS) As[i] = g_A[b][0][i];
    if (tid < KSLOT) cs[tid] = g_c[b][tid];

    // ---- stage x tile: fp32 coalesced load, convert to half2, STS.64 ----
    const float4* src = (const float4*)pf + (size_t)base * 16;
    #pragma unroll 8
    for (int i = 0; i < 32; i++) {
        int idx = tid + i * THREADS;              // 0..4095
        float4 xv = src[idx];
        __half2 h0 = __float22half2_rn(make_float2(xv.x, xv.y));
        __half2 h1 = __float22half2_rn(make_float2(xv.z, xv.w));
        uint2 u;
        u.x = *reinterpret_cast<unsigned*>(&h0);
        u.y = *reinterpret_cast<unsigned*>(&h1);
        int p = idx >> 4, qq = idx & 15;
        xs[p * 17 + qq] = u;
    }
    __syncthreads();

    // ---- phase 1: logits for 2 points/thread, A broadcast shared ----
    float acc0[KSLOT], acc1[KSLOT];
    #pragma unroll
    for (int j = 0; j < KSLOT; j++) { acc0[j] = 0.f; acc1[j] = 0.f; }

    #pragma unroll
    for (int qq = 0; qq < 16; qq++) {
        uint2 ua = xs[tid * 17 + qq];
        uint2 ub = xs[(tid + THREADS) * 17 + qq];
        float2 a01 = __half22float2(*reinterpret_cast<__half2*>(&ua.x));
        float2 a23 = __half22float2(*reinterpret_cast<__half2*>(&ua.y));
        float2 b01 = __half22float2(*reinterpret_cast<__half2*>(&ub.x));
        float2 b23 = __half22float2(*reinterpret_cast<__half2*>(&ub.y));
        #pragma unroll
        for (int j = 0; j < KSLOT; j++) {
            float4 a4 = *(const float4*)&As[j * DDIM + qq * 4];
            acc0[j] = fmaf(a01.x, a4.x, acc0[j]);
            acc0[j] = fmaf(a01.y, a4.y, acc0[j]);
            acc0[j] = fmaf(a23.x, a4.z, acc0[j]);
            acc0[j] = fmaf(a23.y, a4.w, acc0[j]);
            acc1[j] = fmaf(b01.x, a4.x, acc1[j]);
            acc1[j] = fmaf(b01.y, a4.y, acc1[j]);
            acc1[j] = fmaf(b23.x, a4.z, acc1[j]);
            acc1[j] = fmaf(b23.y, a4.w, acc1[j]);
        }
    }

    const float esc = g_esc[0];

    // ---- softmax / sigma / ws for my 2 points ----
    #pragma unroll
    for (int s = 0; s < 2; s++) {
        const int p = tid + s * THREADS;
        const int g = base + p;
        float lg[KSLOT];
        #pragma unroll
        for (int j = 0; j < KSLOT; j++)
            lg[j] = (s == 0 ? acc0[j] : acc1[j]) + cs[j];

        float cx = coor[g * 3 + 0];
        float cy = coor[g * 3 + 1];
        float cz = coor[g * 3 + 2];
        bool oob = (fabsf(cx) > 1.0f) || (fabsf(cy) > 1.0f) || (fabsf(cz) > 1.0f);
        if (oob) {
            #pragma unroll
            for (int j = 2; j < KSLOT; j++) lg[j] = -INFINITY;
        }

        float m = lg[0];
        #pragma unroll
        for (int j = 1; j < KSLOT; j++) m = fmaxf(m, lg[j]);
        float ex[KSLOT], sum = 0.f;
        #pragma unroll
        for (int j = 0; j < KSLOT; j++) { ex[j] = __expf(lg[j] - m); sum += ex[j]; }
        const float inv = 1.0f / sum;

        float sig = 0.f;
        #pragma unroll
        for (int j = 1; j < KSLOT; j++)
            sig = fmaf(fmaxf(lg[j], 0.f), ex[j] * inv, sig);
        sig_out[g] = sig * esc;

        // vectorized ws stores, 48B stride: conflict-free per 8-lane phase
        *(float4*)&ws[p * 12 + 0] = make_float4(ex[0]*inv, ex[1]*inv, ex[2]*inv, ex[3]*inv);
        *(float4*)&ws[p * 12 + 4] = make_float4(ex[4]*inv, ex[5]*inv, ex[6]*inv, ex[7]*inv);
        *(float4*)&ws[p * 12 + 8] = make_float4(ex[8]*inv, 0.f, 0.f, 0.f);
    }
    __syncthreads();

    // ---- coalesced w write: 2304 elems ----
    #pragma unroll
    for (int i = 0; i < (TILE * KSLOT) / THREADS; i++) {   // 18 iters
        int idx = tid + i * THREADS;
        int p = idx / KSLOT, jj = idx - p * KSLOT;
        w_out[(size_t)base * KSLOT + idx] = ws[p * 12 + jj];
    }

    // ---- phase 2: xo, 16 threads per point (V loaded here: short live range) ----
    const int q  = tid & 15;
    const int pg = tid >> 4;                 // 0..7
    float4 v[KSLOT];
    #pragma unroll
    for (int j = 0; j < KSLOT; j++)
        v[j] = *(const float4*)&g_V[b][j][q * 4];
    const float4 ob = *(const float4*)&out_b[q * 4];

    #pragma unroll
    for (int it = 0; it < TILE / 8; it++) {  // 32 iters
        int p = pg + it * 8;
        float4 w0 = *(const float4*)&ws[p * 12 + 0];
        float4 w1 = *(const float4*)&ws[p * 12 + 4];
        float  w8 = ws[p * 12 + 8];
        float wv[KSLOT] = {w0.x, w0.y, w0.z, w0.w, w1.x, w1.y, w1.z, w1.w, w8};
        float4 o = ob;
        #pragma unroll
        for (int j = 0; j < KSLOT; j++) {
            o.x = fmaf(wv[j], v[j].x, o.x);
            o.y = fmaf(wv[j], v[j].y, o.y);
            o.z = fmaf(wv[j], v[j].z, o.z);
            o.w = fmaf(wv[j], v[j].w, o.w);
        }
        *(float4*)&xo_out[(size_t)(base + p) * DDIM + q * 4] = o;
    }
}

// ---------------------------------------------------------------------------
extern "C" void kernel_launch(void* const* d_in, const int* in_sizes, int n_in,
                              void* d_out, int out_size) {
    const float* pf    = (const float*)d_in[0];   // point_feats
    // d_in[1] points_emb: unused (identity stand-in in reference)
    const float* slots = (const float*)d_in[2];
    const float* coor  = (const float*)d_in[3];
    const float* empty = (const float*)d_in[4];
    const float* Wq_w  = (const float*)d_in[5];
    const float* Wq_b  = (const float*)d_in[6];
    const float* Wk_w  = (const float*)d_in[7];
    const float* Wk_b  = (const float*)d_in[8];
    const float* out_w = (const float*)d_in[9];
    const float* ob    = (const float*)d_in[10];
    const float* dsc   = (const float*)d_in[11];
    // d_in[12] Nr: unused

    float* out = (float*)d_out;
    float* xo  = out;                                   // [B,N,64]
    float* w   = xo + (size_t)BB * NPTS * DDIM;         // [B,N,9]
    float* sg  = w  + (size_t)BB * NPTS * KSLOT;        // [B,N]

    cudaFuncSetAttribute(main_kernel,
                         cudaFuncAttributeMaxDynamicSharedMemorySize, SMEM_BYTES);

    prep_kernel<<<BB, KSLOT * DDIM>>>(slots, empty, Wq_w, Wq_b, Wk_w, Wk_b,
                                      out_w, dsc);
    main_kernel<<<(BB * NPTS) / TILE, THREADS, SMEM_BYTES>>>(pf, coor, ob, xo, w, sg);
}

// round 4
// speedup vs baseline: 1.1662x; 1.1662x over previous
#include <cuda_runtime.h>
#include <cuda_fp16.h>
#include <math.h>

#define BB     2
#define NPTS   262144
#define KSLOT  9
#define SDIM   64
#define DDIM   64
#define SCALEF 0.125f

#define TILE    128
#define THREADS 128

// Precomputed per-batch tiny matrices (written by prep_kernel).
__device__ float g_A[BB][KSLOT][DDIM];   // SCALE * (k @ Wq_w)   [9,64]
__device__ float g_V[BB][KSLOT][DDIM];   // slots_full @ out_w^T [9,64]
__device__ float g_c[BB][KSLOT];         // SCALE * (Wq_b . k_j)
__device__ float g_esc[1];               // exp(density_scale)

// ---------------------------------------------------------------------------
// Prep: one block per batch, 576 threads = (j,d) pairs.
// ---------------------------------------------------------------------------
__global__ void prep_kernel(const float* __restrict__ slots,
                            const float* __restrict__ empty_slot,
                            const float* __restrict__ Wq_w,
                            const float* __restrict__ Wq_b,
                            const float* __restrict__ Wk_w,
                            const float* __restrict__ Wk_b,
                            const float* __restrict__ out_w,
                            const float* __restrict__ density_scale) {
    int b   = blockIdx.x;
    int tid = threadIdx.x;        // 0..575
    int j   = tid >> 6;
    int d   = tid & 63;

    __shared__ float sf[KSLOT][SDIM];
    __shared__ float sk[KSLOT][DDIM];

    sf[j][d] = (j == 0) ? empty_slot[d]
                        : slots[(b * (KSLOT - 1) + (j - 1)) * SDIM + d];
    __syncthreads();

    float kk = Wk_b[d];
    #pragma unroll
    for (int s = 0; s < SDIM; s++)
        kk = fmaf(sf[j][s], Wk_w[d * SDIM + s], kk);
    sk[j][d] = kk;
    __syncthreads();

    float aa = 0.f;
    #pragma unroll
    for (int e = 0; e < DDIM; e++)
        aa = fmaf(sk[j][e], Wq_w[e * DDIM + d], aa);
    g_A[b][j][d] = aa * SCALEF;

    float vv = 0.f;
    #pragma unroll
    for (int s = 0; s < SDIM; s++)
        vv = fmaf(sf[j][s], out_w[d * SDIM + s], vv);
    g_V[b][j][d] = vv;

    if (tid < KSLOT) {
        float cc = 0.f;
        #pragma unroll
        for (int e = 0; e < DDIM; e++)
            cc = fmaf(Wq_b[e], sk[tid][e], cc);
        g_c[b][tid] = cc * SCALEF;
    }
    if (b == 0 && tid == 0) g_esc[0] = expf(density_scale[0]);
}

// ---------------------------------------------------------------------------
// Main: 128 points per 128-thread block (round-1 shape), x staged as fp16,
// smem 26KB static, reg-capped for 6 CTAs/SM.
// ---------------------------------------------------------------------------
__global__ __launch_bounds__(THREADS, 6)
void main_kernel(const float* __restrict__ pf,     // [B,N,64]
                 const float* __restrict__ coor,   // [B,N,3]
                 const float* __restrict__ out_b,  // [64]
                 float* __restrict__ xo_out,       // [B,N,64]
                 float* __restrict__ w_out,        // [B,N,9]
                 float* __restrict__ sig_out) {    // [B,N]

    __shared__ uint2 xs[TILE * 17];          // fp16 x: 16 used + 1 pad per point
    __shared__ float ws[TILE * 12];          // softmax weights, padded to 12
    __shared__ float As[KSLOT * DDIM];
    __shared__ float cs[KSLOT];

    const int tid  = threadIdx.x;
    const int base = blockIdx.x * TILE;
    const int b    = base / NPTS;            // tiles never straddle batches
    const int g    = base + tid;

    // ---- stage A, c ----
    #pragma unroll
    for (int i = tid; i < KSLOT * DDIM; i += THREADS) As[i] = g_A[b][0][i];
    if (tid < KSLOT) cs[tid] = g_c[b][tid];

    // ---- prefetch coor (independent; hides behind phase 1) ----
    float cx = coor[g * 3 + 0];
    float cy = coor[g * 3 + 1];
    float cz = coor[g * 3 + 2];

    // ---- stage x tile: coalesced float4 loads, convert to fp16, STS.64 ----
    const float4* src = (const float4*)pf + (size_t)base * 16;
    #pragma unroll
    for (int i = 0; i < 16; i++) {
        int idx = tid + i * THREADS;         // 0..2047
        float4 xv = src[idx];
        __half2 h0 = __float22half2_rn(make_float2(xv.x, xv.y));
        __half2 h1 = __float22half2_rn(make_float2(xv.z, xv.w));
        uint2 u;
        u.x = *reinterpret_cast<unsigned*>(&h0);
        u.y = *reinterpret_cast<unsigned*>(&h1);
        int p = idx >> 4, ev = idx & 15;
        xs[p * 17 + ev] = u;
    }
    __syncthreads();

    // ---- phase 1: logits for my point ----
    float acc[KSLOT];
    #pragma unroll
    for (int j = 0; j < KSLOT; j++) acc[j] = cs[j];

    #pragma unroll
    for (int qq = 0; qq < 16; qq++) {
        uint2 u = xs[tid * 17 + qq];
        float2 x01 = __half22float2(*reinterpret_cast<__half2*>(&u.x));
        float2 x23 = __half22float2(*reinterpret_cast<__half2*>(&u.y));
        #pragma unroll
        for (int j = 0; j < KSLOT; j++) {
            float4 a4 = *(const float4*)&As[j * DDIM + qq * 4];
            acc[j] = fmaf(x01.x, a4.x, acc[j]);
            acc[j] = fmaf(x01.y, a4.y, acc[j]);
            acc[j] = fmaf(x23.x, a4.z, acc[j]);
            acc[j] = fmaf(x23.y, a4.w, acc[j]);
        }
    }

    bool oob = (fabsf(cx) > 1.0f) || (fabsf(cy) > 1.0f) || (fabsf(cz) > 1.0f);
    if (oob) {
        #pragma unroll
        for (int j = 2; j < KSLOT; j++) acc[j] = -INFINITY;
    }

    float m = acc[0];
    #pragma unroll
    for (int j = 1; j < KSLOT; j++) m = fmaxf(m, acc[j]);
    float ex[KSLOT], sum = 0.f;
    #pragma unroll
    for (int j = 0; j < KSLOT; j++) { ex[j] = __expf(acc[j] - m); sum += ex[j]; }
    const float inv = 1.0f / sum;

    float sig = 0.f;
    #pragma unroll
    for (int j = 1; j < KSLOT; j++)
        sig = fmaf(fmaxf(acc[j], 0.f), ex[j] * inv, sig);
    sig_out[g] = sig * g_esc[0];

    // vectorized ws stores (48B stride: conflict-free per 8-lane phase)
    *(float4*)&ws[tid * 12 + 0] = make_float4(ex[0]*inv, ex[1]*inv, ex[2]*inv, ex[3]*inv);
    *(float4*)&ws[tid * 12 + 4] = make_float4(ex[4]*inv, ex[5]*inv, ex[6]*inv, ex[7]*inv);
    *(float4*)&ws[tid * 12 + 8] = make_float4(ex[8]*inv, 0.f, 0.f, 0.f);

    __syncthreads();

    // ---- coalesced w write: 1152 elems ----
    #pragma unroll
    for (int i = 0; i < (TILE * KSLOT) / THREADS; i++) {   // 9 iters
        int idx = tid + i * THREADS;
        int p = idx / KSLOT, jj = idx - p * KSLOT;
        w_out[(size_t)base * KSLOT + idx] = ws[p * 12 + jj];
    }

    // ---- phase 2: xo, 16 threads per point (V loaded here: short live range) ----
    const int q  = tid & 15;
    const int pg = tid >> 4;                 // 0..7
    float4 v[KSLOT];
    #pragma unroll
    for (int j = 0; j < KSLOT; j++)
        v[j] = *(const float4*)&g_V[b][j][q * 4];
    const float4 ob = *(const float4*)&out_b[q * 4];

    #pragma unroll
    for (int it = 0; it < TILE / 8; it++) {  // 16 iters
        int p = pg + it * 8;
        float4 w0 = *(const float4*)&ws[p * 12 + 0];
        float4 w1 = *(const float4*)&ws[p * 12 + 4];
        float  w8 = ws[p * 12 + 8];
        float wv[KSLOT] = {w0.x, w0.y, w0.z, w0.w, w1.x, w1.y, w1.z, w1.w, w8};
        float4 o = ob;
        #pragma unroll
        for (int j = 0; j < KSLOT; j++) {
            o.x = fmaf(wv[j], v[j].x, o.x);
            o.y = fmaf(wv[j], v[j].y, o.y);
            o.z = fmaf(wv[j], v[j].z, o.z);
            o.w = fmaf(wv[j], v[j].w, o.w);
        }
        *(float4*)&xo_out[(size_t)(base + p) * DDIM + q * 4] = o;
    }
}

// ---------------------------------------------------------------------------
extern "C" void kernel_launch(void* const* d_in, const int* in_sizes, int n_in,
                              void* d_out, int out_size) {
    const float* pf    = (const float*)d_in[0];   // point_feats
    // d_in[1] points_emb: unused (identity stand-in in reference)
    const float* slots = (const float*)d_in[2];
    const float* coor  = (const float*)d_in[3];
    const float* empty = (const float*)d_in[4];
    const float* Wq_w  = (const float*)d_in[5];
    const float* Wq_b  = (const float*)d_in[6];
    const float* Wk_w  = (const float*)d_in[7];
    const float* Wk_b  = (const float*)d_in[8];
    const float* out_w = (const float*)d_in[9];
    const float* ob    = (const float*)d_in[10];
    const float* dsc   = (const float*)d_in[11];
    // d_in[12] Nr: unused

    float* out = (float*)d_out;
    float* xo  = out;                                   // [B,N,64]
    float* w   = xo + (size_t)BB * NPTS * DDIM;         // [B,N,9]
    float* sg  = w  + (size_t)BB * NPTS * KSLOT;        // [B,N]

    prep_kernel<<<BB, KSLOT * DDIM>>>(slots, empty, Wq_w, Wq_b, Wk_w, Wk_b,
                                      out_w, dsc);
    main_kernel<<<(BB * NPTS) / TILE, THREADS>>>(pf, coor, ob, xo, w, sg);
}